// round 1
// baseline (speedup 1.0000x reference)
#include <cuda_runtime.h>
#include <math.h>

// Problem: Attn_9637906612873
// out layout (concatenated reference returns):
//   [0 .. B*TQ*DOUT)             : output     [32,1024,1024] f32
//   [B*TQ*DOUT .. +B*TQ*L)       : attn_wts   [32,1024,2048] f32
#define NB  32
#define NTQ 1024
#define NL  2048
#define ND  1024

// Scratch (allocation-free rule: __device__ globals)
static __device__ float g_Qm   [(size_t)NB * NTQ * ND];  // Q @ Wq^T + bq
static __device__ float g_attnA[(size_t)NB * NTQ * ND];  // attn @ V
static __device__ float g_attnW[(size_t)NB * NTQ * NL];  // fallback attn buffer

// ---------------------------------------------------------------------------
// 128x128x16 SGEMM tile, 256 threads, 8x8 per thread.
//   C[m,n] (+)= sum_k A[m,k] * B'[k,n]  (+ bias[n])
//   BKMAJ=true : B stored [N,K] K-contiguous (row n, stride ldb)  -> "TN"
//   BKMAJ=false: B stored [K,N] N-contiguous (row k, stride ldb)  -> "NN"
// All dims used here are multiples of 128 (M,N) and 16 (K): no bounds checks.
// ---------------------------------------------------------------------------
template<bool BKMAJ, bool BIAS, bool ACCUM>
__global__ __launch_bounds__(256, 2)
void gemm128(const float* __restrict__ A, const float* __restrict__ Bm,
             const float* __restrict__ bias, float* __restrict__ C,
             int Kdim, int lda, int ldb, int ldc,
             long long sA, long long sB, long long sC)
{
    A  += (long long)blockIdx.z * sA;
    Bm += (long long)blockIdx.z * sB;
    C  += (long long)blockIdx.z * sC;

    __shared__ float As[16][128];   // As[k][m]
    __shared__ float Bs[16][128];   // Bs[k][n]

    const int tid = threadIdx.x;
    const int tx = tid & 15;
    const int ty = tid >> 4;
    const long long m0 = (long long)blockIdx.y * 128;
    const int n0 = blockIdx.x * 128;

    // A loader: 2 float4 per thread; row = tid>>1, k-offset = (tid&1)*8
    const int arow = tid >> 1;
    const int ak0  = (tid & 1) * 8;
    const float* Aptr = A + (m0 + arow) * (long long)lda + ak0;

    // B loader
    const float* BptrT = Bm + (long long)(n0 + arow) * ldb + ak0;      // K-major
    const int bk = tid >> 5;          // 0..7
    const int bn = (tid & 31) * 4;    // 0..124
    const float* BptrN = Bm + (long long)bk * ldb + n0 + bn;           // N-major

    float acc[8][8];
    #pragma unroll
    for (int i = 0; i < 8; i++)
        #pragma unroll
        for (int j = 0; j < 8; j++) acc[i][j] = 0.f;

    for (int k0 = 0; k0 < Kdim; k0 += 16) {
        // global -> regs
        float4 a0 = *(const float4*)(Aptr + k0);
        float4 a1 = *(const float4*)(Aptr + k0 + 4);
        float4 b0, b1;
        if (BKMAJ) {
            b0 = *(const float4*)(BptrT + k0);
            b1 = *(const float4*)(BptrT + k0 + 4);
        } else {
            b0 = *(const float4*)(BptrN + (long long)k0 * ldb);
            b1 = *(const float4*)(BptrN + (long long)(k0 + 8) * ldb);
        }
        __syncthreads();   // previous tile's compute done
        // regs -> smem (A transposed to [k][m])
        As[ak0 + 0][arow] = a0.x;  As[ak0 + 1][arow] = a0.y;
        As[ak0 + 2][arow] = a0.z;  As[ak0 + 3][arow] = a0.w;
        As[ak0 + 4][arow] = a1.x;  As[ak0 + 5][arow] = a1.y;
        As[ak0 + 6][arow] = a1.z;  As[ak0 + 7][arow] = a1.w;
        if (BKMAJ) {
            Bs[ak0 + 0][arow] = b0.x;  Bs[ak0 + 1][arow] = b0.y;
            Bs[ak0 + 2][arow] = b0.z;  Bs[ak0 + 3][arow] = b0.w;
            Bs[ak0 + 4][arow] = b1.x;  Bs[ak0 + 5][arow] = b1.y;
            Bs[ak0 + 6][arow] = b1.z;  Bs[ak0 + 7][arow] = b1.w;
        } else {
            *(float4*)&Bs[bk    ][bn] = b0;
            *(float4*)&Bs[bk + 8][bn] = b1;
        }
        __syncthreads();

        #pragma unroll 4
        for (int kk = 0; kk < 16; kk++) {
            float a[8], b[8];
            *(float4*)&a[0] = *(const float4*)&As[kk][ty * 4];
            *(float4*)&a[4] = *(const float4*)&As[kk][64 + ty * 4];
            *(float4*)&b[0] = *(const float4*)&Bs[kk][tx * 4];
            *(float4*)&b[4] = *(const float4*)&Bs[kk][64 + tx * 4];
            #pragma unroll
            for (int i = 0; i < 8; i++)
                #pragma unroll
                for (int j = 0; j < 8; j++)
                    acc[i][j] = fmaf(a[i], b[j], acc[i][j]);
        }
    }

    float bv[8];
    if (BIAS) {
        #pragma unroll
        for (int j = 0; j < 8; j++) {
            int nn = n0 + ((j < 4) ? (tx * 4 + j) : (64 + tx * 4 + (j - 4)));
            bv[j] = bias[nn];
        }
    }

    #pragma unroll
    for (int i = 0; i < 8; i++) {
        long long m = m0 + ((i < 4) ? (ty * 4 + i) : (64 + ty * 4 + (i - 4)));
        float* crow = C + m * (long long)ldc + n0;
        float4 v0, v1;
        v0.x = acc[i][0]; v0.y = acc[i][1]; v0.z = acc[i][2]; v0.w = acc[i][3];
        v1.x = acc[i][4]; v1.y = acc[i][5]; v1.z = acc[i][6]; v1.w = acc[i][7];
        if (BIAS) {
            v0.x += bv[0]; v0.y += bv[1]; v0.z += bv[2]; v0.w += bv[3];
            v1.x += bv[4]; v1.y += bv[5]; v1.z += bv[6]; v1.w += bv[7];
        }
        if (ACCUM) {
            float4 o0 = *(const float4*)(crow + tx * 4);
            float4 o1 = *(const float4*)(crow + 64 + tx * 4);
            v0.x += o0.x; v0.y += o0.y; v0.z += o0.z; v0.w += o0.w;
            v1.x += o1.x; v1.y += o1.y; v1.z += o1.z; v1.w += o1.w;
        }
        *(float4*)(crow + tx * 4)      = v0;
        *(float4*)(crow + 64 + tx * 4) = v1;
    }
}

// ---------------------------------------------------------------------------
// In-place row softmax over NL=2048 columns; one block (256 thr) per row.
// Scores have std ~32 -> max-subtraction mandatory.
// ---------------------------------------------------------------------------
__global__ __launch_bounds__(256)
void softmax2048(float* __restrict__ S)
{
    float* p = S + (long long)blockIdx.x * NL;
    const int tid  = threadIdx.x;
    const int lane = tid & 31;
    const int wid  = tid >> 5;

    float4 v0 = ((const float4*)p)[tid];
    float4 v1 = ((const float4*)p)[tid + 256];

    float mx = fmaxf(fmaxf(fmaxf(v0.x, v0.y), fmaxf(v0.z, v0.w)),
                     fmaxf(fmaxf(v1.x, v1.y), fmaxf(v1.z, v1.w)));
    __shared__ float red[8];
    __shared__ float bval;
    #pragma unroll
    for (int o = 16; o > 0; o >>= 1) mx = fmaxf(mx, __shfl_xor_sync(0xffffffffu, mx, o));
    if (lane == 0) red[wid] = mx;
    __syncthreads();
    if (tid == 0) {
        float m = red[0];
        #pragma unroll
        for (int i = 1; i < 8; i++) m = fmaxf(m, red[i]);
        bval = m;
    }
    __syncthreads();
    mx = bval;

    v0.x = expf(v0.x - mx); v0.y = expf(v0.y - mx);
    v0.z = expf(v0.z - mx); v0.w = expf(v0.w - mx);
    v1.x = expf(v1.x - mx); v1.y = expf(v1.y - mx);
    v1.z = expf(v1.z - mx); v1.w = expf(v1.w - mx);

    float s = (v0.x + v0.y + v0.z + v0.w) + (v1.x + v1.y + v1.z + v1.w);
    #pragma unroll
    for (int o = 16; o > 0; o >>= 1) s += __shfl_xor_sync(0xffffffffu, s, o);
    if (lane == 0) red[wid] = s;
    __syncthreads();
    if (tid == 0) {
        float t = red[0];
        #pragma unroll
        for (int i = 1; i < 8; i++) t += red[i];
        bval = 1.f / t;
    }
    __syncthreads();
    float inv = bval;

    v0.x *= inv; v0.y *= inv; v0.z *= inv; v0.w *= inv;
    v1.x *= inv; v1.y *= inv; v1.z *= inv; v1.w *= inv;
    ((float4*)p)[tid]       = v0;
    ((float4*)p)[tid + 256] = v1;
}

extern "C" void kernel_launch(void* const* d_in, const int* in_sizes, int n_in,
                              void* d_out, int out_size)
{
    (void)in_sizes; (void)n_in;
    const float* Q   = (const float*)d_in[0];
    const float* Kin = (const float*)d_in[1];
    const float* V   = (const float*)d_in[2];
    const float* Wq  = (const float*)d_in[3];
    const float* bq  = (const float*)d_in[4];
    const float* Wc  = (const float*)d_in[5];
    const float* bc  = (const float*)d_in[6];
    float* out = (float*)d_out;

    float *Qm, *attnA, *attnW;
    cudaGetSymbolAddress((void**)&Qm,    g_Qm);
    cudaGetSymbolAddress((void**)&attnA, g_attnA);
    cudaGetSymbolAddress((void**)&attnW, g_attnW);

    const long long outElems  = (long long)NB * NTQ * ND;   // 33554432
    const long long attnElems = (long long)NB * NTQ * NL;   // 67108864
    // attn_weights is the 2nd flattened output; fall back to scratch if the
    // harness only sized d_out for `output`.
    float* attn = ((long long)out_size >= outElems + attnElems) ? (out + outElems)
                                                                : attnW;

    // 1) Q_mapped = Q @ Wq^T + bq            [32768,1024] x [1024,1024]^T
    gemm128<true, true, false><<<dim3(ND / 128, (NB * NTQ) / 128, 1), 256>>>(
        Q, Wq, bq, Qm, ND, ND, ND, ND, 0, 0, 0);

    // 2) scores[b] = Qm[b] @ K[b]^T          per-batch [1024,1024]x[2048,1024]^T
    gemm128<true, false, false><<<dim3(NL / 128, NTQ / 128, NB), 256>>>(
        Qm, Kin, nullptr, attn, ND, ND, ND, NL,
        (long long)NTQ * ND, (long long)NL * ND, (long long)NTQ * NL);

    // 3) softmax rows (in place -> attn_weights output)
    softmax2048<<<NB * NTQ, 256>>>(attn);

    // 4) attnA[b] = attn[b] @ V[b]           [1024,2048] x [2048,1024] (NN)
    gemm128<false, false, false><<<dim3(ND / 128, NTQ / 128, NB), 256>>>(
        attn, V, nullptr, attnA, NL, NL, ND, ND,
        (long long)NTQ * NL, (long long)NL * ND, (long long)NTQ * ND);

    // 5) output = Q @ Wc[:, :1024]^T + bc
    gemm128<true, true, false><<<dim3(ND / 128, (NB * NTQ) / 128, 1), 256>>>(
        Q, Wc, bc, out, ND, ND, 2 * ND, ND, 0, 0, 0);

    // 6) output += attnA @ Wc[:, 1024:]^T
    gemm128<true, false, true><<<dim3(ND / 128, (NB * NTQ) / 128, 1), 256>>>(
        attnA, Wc + ND, nullptr, out, ND, ND, 2 * ND, ND, 0, 0, 0);
}